// round 12
// baseline (speedup 1.0000x reference)
#include <cuda_runtime.h>
#include <math.h>
#include <float.h>

// ---------------- problem constants ----------------
#define NNODES 1024
#define NPGC   128
#define NBG    8
#define KNBR   64
#define HDIM   600
#define GDIM   50
#define LAY    6
#define NEDGE  (NNODES*KNBR)   // 65536
#define EA_LD  52              // gaussian features padded 50 -> 52 (16B-aligned rows)

// ---------------- scratch (static device globals; no allocation) ----------------
__device__ float g_A[NEDGE * HDIM];        // ssp(ea@W1+b1), per layer (157 MB)
__device__ float g_eattr[NEDGE * EA_LD];   // gaussian smearing (13.6 MB)
__device__ float g_h[2][NNODES * HDIM];    // node features ping-pong
__device__ float g_x1[NNODES * HDIM];
__device__ float g_msg[NNODES * HDIM];
__device__ float g_t[NNODES * HDIM];
__device__ int   g_nbr[NEDGE];
__device__ float g_C[NEDGE];
__device__ float g_d[NEDGE];
__device__ float g_pooled[NBG * HDIM];

// ---------------- packed f32x2 helpers ----------------
__device__ __forceinline__ void fma2(unsigned long long& d,
                                     unsigned long long a,
                                     unsigned long long b) {
    asm("fma.rn.f32x2 %0, %1, %2, %0;" : "+l"(d) : "l"(a), "l"(b));
}
__device__ __forceinline__ void unpack2(unsigned long long v, float& lo, float& hi) {
    asm("mov.b64 {%0, %1}, %2;" : "=f"(lo), "=f"(hi) : "l"(v));
}

// ---------------- shifted softplus ----------------
__device__ __forceinline__ float sspf(float x) {
    float u = x * x;
    if (u < 1.0f) {
        float p = fmaf(u, -2.6356299e-5f, 3.4722222e-4f);
        p = fmaf(u, p, -5.2083333e-3f);
        p = fmaf(u, p, 0.125f);
        return fmaf(u, p, 0.5f * x);
    }
    return fmaxf(x, 0.f) + log1pf(expf(-fabsf(x))) - 0.69314718056f;
}

// ---------------- graph build: one warp per node ----------------
__global__ void build_graph_kernel(const float* __restrict__ pos,
                                   int* __restrict__ nbr,
                                   float* __restrict__ dbuf,
                                   float* __restrict__ cbuf) {
    __shared__ float spos[NPGC * 3];
    const int t = threadIdx.x;
    const int w = t >> 5, lane = t & 31;
    const int node = blockIdx.x * 8 + w;
    const int g = node >> 7;
    const int i = node & 127;

    for (int idx = t; idx < NPGC * 3; idx += blockDim.x)
        spos[idx] = pos[g * NPGC * 3 + idx];
    __syncthreads();

    const float px = spos[i*3+0], py = spos[i*3+1], pz = spos[i*3+2];
    float d2v[4];
#pragma unroll
    for (int c = 0; c < 4; c++) {
        int j = lane + 32 * c;
        float dx = px - spos[j*3+0];
        float dy = py - spos[j*3+1];
        float dz = pz - spos[j*3+2];
        float d2 = fmaf(dx, dx, fmaf(dy, dy, dz * dz));
        bool ok = (j != i) && (d2 <= 100.0f);
        d2v[c] = ok ? d2 : FLT_MAX;
    }

    const float PIF = 3.14159265358979f;
    for (int slot = 0; slot < KNBR; slot++) {
        float mv = d2v[0]; int mc = 0;
#pragma unroll
        for (int c = 1; c < 4; c++) if (d2v[c] < mv) { mv = d2v[c]; mc = c; }
        int mj = lane + 32 * mc;
#pragma unroll
        for (int off = 16; off > 0; off >>= 1) {
            float ov = __shfl_down_sync(0xFFFFFFFFu, mv, off);
            int   oj = __shfl_down_sync(0xFFFFFFFFu, mj, off);
            if (ov < mv || (ov == mv && oj < mj)) { mv = ov; mj = oj; }
        }
        mv = __shfl_sync(0xFFFFFFFFu, mv, 0);
        mj = __shfl_sync(0xFFFFFFFFu, mj, 0);
        if (lane == (mj & 31)) d2v[mj >> 5] = FLT_MAX;
        if (lane == 0) {
            int e = node * KNBR + slot;
            if (mv < 1e37f) {
                nbr[e] = g * NPGC + mj;
                float d = sqrtf(mv);
                dbuf[e] = d;
                cbuf[e] = 0.5f * (cosf(d * PIF / 10.0f) + 1.0f);
            } else {
                nbr[e] = node;
                dbuf[e] = 0.f;
                cbuf[e] = 0.f;
            }
        }
    }
}

// ---------------- gaussian smearing ----------------
__global__ void edge_feat_kernel(const float* __restrict__ dbuf,
                                 float* __restrict__ eattr) {
    int idx = blockIdx.x * blockDim.x + threadIdx.x;
    if (idx >= NEDGE * EA_LD) return;
    int e = idx / EA_LD;
    int c = idx - e * EA_LD;
    float v = 0.f;
    if (c < GDIM) {
        const float step = 10.0f / 49.0f;
        const float coeff = -0.5f / (step * step);
        float t = dbuf[e] - c * step;
        v = __expf(coeff * t * t);
    }
    eattr[idx] = v;
}

// ---------------- embedding gather ----------------
__global__ void embed_kernel(const float* __restrict__ emb,
                             const int* __restrict__ z,
                             float* __restrict__ h) {
    int idx = blockIdx.x * blockDim.x + threadIdx.x;
    if (idx >= NNODES * HDIM) return;
    int n = idx / HDIM, c = idx - n * HDIM;
    h[idx] = emb[z[n] * HDIM + c];
}

// ---------------- GEMM (f32x2 packed): out[M x 600] = X[M x kx] @ W[kw x 600] (+epi)
// BMT = 128 (RPT=8) or 64 (RPT=4). BN=64, BK=16, 256 threads.
// Accumulators paired along rows -> a-pairs free from smem; b duplicated in smem.
// EPI: 0 = plain, 1 = ssp(acc + bias), 2 = res + acc + bias
#define BM 128
#define BN 64
#define BK 16

template<int EPI, int BMT>
__global__ __launch_bounds__(256) void gemm_kernel(
    const float* __restrict__ X, int ldx, int kx, int kw,
    const float* __restrict__ W,
    const float* __restrict__ bias,
    const float* __restrict__ res,
    float* __restrict__ out)
{
    constexpr int RPT = BMT / 16;    // rows per thread: 8 or 4
    constexpr int NP  = RPT / 2;     // row pairs: 4 or 2
    constexpr int NXV = RPT / 4;     // float4s per X load: 2 or 1
    constexpr int TPR = 16 / RPT;    // threads per X row: 2 or 4

    __shared__ float Xs[BK][BMT + 4];
    __shared__ float Wsd[BK][2 * BN + 8];

    const int t = threadIdx.x;
    const int ty = t >> 4, tx = t & 15;
    const int row0 = blockIdx.x * BMT;
    const int h0 = blockIdx.y * BN;

    unsigned long long acc2[NP][4];
#pragma unroll
    for (int p = 0; p < NP; p++)
#pragma unroll
        for (int j = 0; j < 4; j++) acc2[p][j] = 0ull;

    const int kmax = (kx > kw) ? kx : kw;
    const int nStages = (kmax + BK - 1) / BK;

    const int xrl = t / TPR;
    const int xkoff = (t % TPR) * RPT;
    const float* Xrow = X + (size_t)(row0 + xrl) * ldx;
    const int wk = ty;
    const int wcol = tx * 4;
    const bool wcolOk = (h0 + wcol) < HDIM;

    float4 xr[NXV];
    float4 wr;
    const float4 f4z = make_float4(0.f, 0.f, 0.f, 0.f);

    auto loadStage = [&](int k0) {
#pragma unroll
        for (int q = 0; q < NXV; q++) {
            int kc = k0 + xkoff + 4 * q;
            xr[q] = (kc < kx) ? *(const float4*)(Xrow + kc) : f4z;
        }
        int kr = k0 + wk;
        wr = (kr < kw && wcolOk) ? *(const float4*)(W + (size_t)kr * HDIM + h0 + wcol) : f4z;
    };
    auto stsStage = [&]() {
#pragma unroll
        for (int q = 0; q < NXV; q++) {
#pragma unroll
            for (int j = 0; j < 4; j++) Xs[xkoff + 4 * q + j][xrl] = (&xr[q].x)[j];
        }
        float4 lo = make_float4(wr.x, wr.x, wr.y, wr.y);
        float4 hi = make_float4(wr.z, wr.z, wr.w, wr.w);
        *(float4*)&Wsd[wk][2 * wcol]     = lo;
        *(float4*)&Wsd[wk][2 * wcol + 4] = hi;
    };

    loadStage(0);
    stsStage();
    __syncthreads();

    for (int s = 0; s < nStages; ++s) {
        if (s + 1 < nStages) loadStage((s + 1) * BK);
#pragma unroll
        for (int kk = 0; kk < BK; ++kk) {
            ulonglong2 b01 = *(const ulonglong2*)&Wsd[kk][tx * 8];
            ulonglong2 b23 = *(const ulonglong2*)&Wsd[kk][tx * 8 + 4];
            unsigned long long bd[4] = {b01.x, b01.y, b23.x, b23.y};
            unsigned long long ap[NP];
#pragma unroll
            for (int q = 0; q < NXV; q++) {
                ulonglong2 a = *(const ulonglong2*)&Xs[kk][ty * RPT + 4 * q];
                ap[2 * q] = a.x; ap[2 * q + 1] = a.y;
            }
#pragma unroll
            for (int p = 0; p < NP; p++) {
                fma2(acc2[p][0], ap[p], bd[0]);
                fma2(acc2[p][1], ap[p], bd[1]);
                fma2(acc2[p][2], ap[p], bd[2]);
                fma2(acc2[p][3], ap[p], bd[3]);
            }
        }
        __syncthreads();
        if (s + 1 < nStages) { stsStage(); __syncthreads(); }
    }

    if (!wcolOk) return;
    float acc[RPT][4];
#pragma unroll
    for (int p = 0; p < NP; p++)
#pragma unroll
        for (int j = 0; j < 4; j++)
            unpack2(acc2[p][j], acc[2 * p][j], acc[2 * p + 1][j]);

    float4 bb = f4z;
    if (EPI >= 1) bb = *(const float4*)&bias[h0 + wcol];
#pragma unroll
    for (int i = 0; i < RPT; i++) {
        size_t r = (size_t)(row0 + ty * RPT + i);
        float4 v;
        v.x = acc[i][0] + bb.x; v.y = acc[i][1] + bb.y;
        v.z = acc[i][2] + bb.z; v.w = acc[i][3] + bb.w;
        if (EPI == 1) { v.x = sspf(v.x); v.y = sspf(v.y); v.z = sspf(v.z); v.w = sspf(v.w); }
        if (EPI == 2) {
            float4 rv = *(const float4*)&res[r * HDIM + h0 + wcol];
            v.x += rv.x; v.y += rv.y; v.z += rv.z; v.w += rv.w;
        }
        *(float4*)&out[r * HDIM + h0 + wcol] = v;
    }
}

// ---------------- fused edge GEMM + aggregate (f32x2 packed) ----------------
// block = 2 nodes (128 edges) x 64 h-cols:
// Wf = A@W2 + b2 ; msg[n,h] = sum_k C[e] * x1[nbr[e],h] * Wf[e,h]
__global__ __launch_bounds__(256) void edge_agg_kernel(
    const float* __restrict__ A, const float* __restrict__ W2,
    const float* __restrict__ b2, const float* __restrict__ x1,
    const int* __restrict__ nbr, const float* __restrict__ C,
    float* __restrict__ msg)
{
    __shared__ float Xs[BK][BM + 4];
    __shared__ float Wsd[BK][2 * BN + 8];
    __shared__ float red[16][BN + 4];
    const int t = threadIdx.x;
    const int ty = t >> 4, tx = t & 15;
    const int erow0 = blockIdx.x * BM;
    const int h0 = blockIdx.y * BN;

    unsigned long long acc2[4][4];
#pragma unroll
    for (int p = 0; p < 4; p++)
#pragma unroll
        for (int j = 0; j < 4; j++) acc2[p][j] = 0ull;

    const int nStages = (HDIM + BK - 1) / BK;   // 38
    const int xkoff = (t & 1) * 8;
    const float* Xrow = A + (size_t)(erow0 + (t >> 1)) * HDIM;
    const int wk = ty;
    const int wcol = tx * 4;
    const bool wcolOk = (h0 + wcol) < HDIM;

    float4 xr0, xr1, wr;
    const float4 f4z = make_float4(0.f, 0.f, 0.f, 0.f);

    auto loadStage = [&](int k0) {
        int kc = k0 + xkoff;
        xr0 = (kc < HDIM) ? *(const float4*)(Xrow + kc) : f4z;
        xr1 = (kc + 4 < HDIM) ? *(const float4*)(Xrow + kc + 4) : f4z;
        int kr = k0 + wk;
        wr = (kr < HDIM && wcolOk) ? *(const float4*)(W2 + (size_t)kr * HDIM + h0 + wcol) : f4z;
    };
    auto stsStage = [&]() {
        int rl = t >> 1;
#pragma unroll
        for (int j = 0; j < 4; j++) Xs[xkoff + j][rl] = (&xr0.x)[j];
#pragma unroll
        for (int j = 0; j < 4; j++) Xs[xkoff + 4 + j][rl] = (&xr1.x)[j];
        float4 lo = make_float4(wr.x, wr.x, wr.y, wr.y);
        float4 hi = make_float4(wr.z, wr.z, wr.w, wr.w);
        *(float4*)&Wsd[wk][2 * wcol]     = lo;
        *(float4*)&Wsd[wk][2 * wcol + 4] = hi;
    };

    loadStage(0);
    stsStage();
    __syncthreads();

    for (int s = 0; s < nStages; ++s) {
        if (s + 1 < nStages) loadStage((s + 1) * BK);
#pragma unroll
        for (int kk = 0; kk < BK; ++kk) {
            ulonglong2 b01 = *(const ulonglong2*)&Wsd[kk][tx * 8];
            ulonglong2 b23 = *(const ulonglong2*)&Wsd[kk][tx * 8 + 4];
            unsigned long long bd[4] = {b01.x, b01.y, b23.x, b23.y};
            unsigned long long ap[4];
            {
                ulonglong2 a0 = *(const ulonglong2*)&Xs[kk][ty * 8];
                ulonglong2 a1 = *(const ulonglong2*)&Xs[kk][ty * 8 + 4];
                ap[0] = a0.x; ap[1] = a0.y; ap[2] = a1.x; ap[3] = a1.y;
            }
#pragma unroll
            for (int p = 0; p < 4; p++) {
                fma2(acc2[p][0], ap[p], bd[0]);
                fma2(acc2[p][1], ap[p], bd[1]);
                fma2(acc2[p][2], ap[p], bd[2]);
                fma2(acc2[p][3], ap[p], bd[3]);
            }
        }
        __syncthreads();
        if (s + 1 < nStages) { stsStage(); __syncthreads(); }
    }

    float acc[8][4];
#pragma unroll
    for (int p = 0; p < 4; p++)
#pragma unroll
        for (int j = 0; j < 4; j++)
            unpack2(acc2[p][j], acc[2 * p][j], acc[2 * p + 1][j]);

    // epilogue: +b2, *C, *x1[nbr], reduce over edges-within-node
    float part[4] = {0.f, 0.f, 0.f, 0.f};
    float4 bb = wcolOk ? *(const float4*)&b2[h0 + wcol] : f4z;
    if (wcolOk) {
#pragma unroll
        for (int i = 0; i < 8; i++) {
            int e = erow0 + ty * 8 + i;
            float ce = C[e];
            if (ce != 0.f) {
                int nb = nbr[e];
                float4 xv = *(const float4*)&x1[(size_t)nb * HDIM + h0 + wcol];
                part[0] = fmaf((acc[i][0] + bb.x) * ce, xv.x, part[0]);
                part[1] = fmaf((acc[i][1] + bb.y) * ce, xv.y, part[1]);
                part[2] = fmaf((acc[i][2] + bb.z) * ce, xv.z, part[2]);
                part[3] = fmaf((acc[i][3] + bb.w) * ce, xv.w, part[3]);
            }
        }
    }
    *(float4*)&red[ty][wcol] = make_float4(part[0], part[1], part[2], part[3]);
    __syncthreads();
    if (t < 128) {
        int half = t >> 6;
        int col = t & 63;
        if (h0 + col < HDIM) {
            float s = 0.f;
#pragma unroll
            for (int i = 0; i < 8; i++) s += red[half * 8 + i][col];
            msg[(size_t)(blockIdx.x * 2 + half) * HDIM + h0 + col] = s;
        }
    }
}

// ---------------- mean pool per graph ----------------
__global__ void pool_kernel(const float* __restrict__ h, float* __restrict__ pooled) {
    int b = blockIdx.x;
    int c = threadIdx.x;
    if (c >= HDIM) return;
    float s = 0.f;
    for (int n = 0; n < NPGC; n++) s += h[(size_t)(b * NPGC + n) * HDIM + c];
    pooled[b * HDIM + c] = s * (1.0f / 128.0f);
}

// ---------------- final linear ----------------
__global__ void out_kernel(const float* __restrict__ pooled,
                           const float* __restrict__ pw,
                           const float* __restrict__ pb,
                           float* __restrict__ out) {
    __shared__ float prow[HDIM];
    int b = blockIdx.x;
    for (int i = threadIdx.x; i < HDIM; i += blockDim.x)
        prow[i] = pooled[b * HDIM + i];
    __syncthreads();
    int c = blockIdx.y * 128 + threadIdx.x;
    if (c < HDIM) {
        float s = pb[c];
        for (int k = 0; k < HDIM; k++)
            s = fmaf(prow[k], pw[k * HDIM + c], s);
        out[b * HDIM + c] = s;
    }
}

// ---------------- host launcher ----------------
extern "C" void kernel_launch(void* const* d_in, const int* in_sizes, int n_in,
                              void* d_out, int out_size) {
    int zi, pi, base;
    if (in_sizes[0] == NNODES) { zi = 0; pi = 1; base = 2; }
    else                       { pi = 0; base = 1; zi = n_in - 1; }

    const int*   z   = (const int*)d_in[zi];
    const float* pos = (const float*)d_in[pi];
    const float* emb = (const float*)d_in[base + 0];
    const float* w1  = (const float*)d_in[base + 1];
    const float* b1  = (const float*)d_in[base + 2];
    const float* w2  = (const float*)d_in[base + 3];
    const float* b2  = (const float*)d_in[base + 4];
    const float* l1w = (const float*)d_in[base + 5];
    const float* l2w = (const float*)d_in[base + 6];
    const float* l2b = (const float*)d_in[base + 7];
    const float* ilw = (const float*)d_in[base + 8];
    const float* ilb = (const float*)d_in[base + 9];
    const float* pw  = (const float*)d_in[base + 10];
    const float* pb  = (const float*)d_in[base + 11];
    float* out = (float*)d_out;

    void* p;
    float *A, *ea, *hbase, *x1, *msgb, *tb, *pooled, *Cb, *db; int* nbrp;
    cudaGetSymbolAddress(&p, g_A);      A = (float*)p;
    cudaGetSymbolAddress(&p, g_eattr);  ea = (float*)p;
    cudaGetSymbolAddress(&p, g_h);      hbase = (float*)p;
    cudaGetSymbolAddress(&p, g_x1);     x1 = (float*)p;
    cudaGetSymbolAddress(&p, g_msg);    msgb = (float*)p;
    cudaGetSymbolAddress(&p, g_t);      tb = (float*)p;
    cudaGetSymbolAddress(&p, g_nbr);    nbrp = (int*)p;
    cudaGetSymbolAddress(&p, g_C);      Cb = (float*)p;
    cudaGetSymbolAddress(&p, g_d);      db = (float*)p;
    cudaGetSymbolAddress(&p, g_pooled); pooled = (float*)p;

    float* h0 = hbase;
    float* h1 = hbase + (size_t)NNODES * HDIM;

    build_graph_kernel<<<128, 256>>>(pos, nbrp, db, Cb);
    edge_feat_kernel<<<(NEDGE * EA_LD + 255) / 256, 256>>>(db, ea);
    embed_kernel<<<(NNODES * HDIM + 255) / 256, 256>>>(emb, z, h0);

    float* hc = h0;
    float* hn = h1;
    for (int l = 0; l < LAY; l++) {
        // x1 = h @ lin1_w (no bias) — BM=64 for occupancy (16x10 = 160 blocks)
        gemm_kernel<0, 64><<<dim3(NNODES / 64, 10), 256>>>(
            hc, HDIM, HDIM, HDIM, l1w + (size_t)l * HDIM * HDIM, nullptr, nullptr, x1);
        // A = ssp(ea @ W1 + b1) — 512x10 blocks
        gemm_kernel<1, 128><<<dim3(NEDGE / 128, 10), 256>>>(
            ea, EA_LD, EA_LD, GDIM, w1 + (size_t)l * GDIM * HDIM, b1 + l * HDIM, nullptr, A);
        // msg = sum_k C * x1[nbr] * (A @ W2 + b2)
        edge_agg_kernel<<<dim3(NNODES / 2, 10), 256>>>(
            A, w2 + (size_t)l * HDIM * HDIM, b2 + l * HDIM, x1, nbrp, Cb, msgb);
        // t = ssp(msg @ lin2_w + lin2_b)
        gemm_kernel<1, 64><<<dim3(NNODES / 64, 10), 256>>>(
            msgb, HDIM, HDIM, HDIM, l2w + (size_t)l * HDIM * HDIM, l2b + l * HDIM, nullptr, tb);
        // h_new = h + t @ int_lin_w + int_lin_b
        gemm_kernel<2, 64><<<dim3(NNODES / 64, 10), 256>>>(
            tb, HDIM, HDIM, HDIM, ilw + (size_t)l * HDIM * HDIM, ilb + l * HDIM, hc, hn);
        float* tmp = hc; hc = hn; hn = tmp;
    }

    pool_kernel<<<NBG, 640>>>(hc, pooled);
    out_kernel<<<dim3(NBG, 5), 128>>>(pooled, pw, pb, out);
}

// round 14
// speedup vs baseline: 3.1563x; 3.1563x over previous
#include <cuda_runtime.h>
#include <math.h>
#include <float.h>

// ---------------- problem constants ----------------
#define NNODES 1024
#define NPGC   128
#define NBG    8
#define KNBR   64
#define HDIM   600
#define GDIM   50
#define LAY    6
#define NEDGE  (NNODES*KNBR)   // 65536
#define EA_LD  52              // gaussian features padded 50 -> 52 (16B-aligned rows)

// ---------------- scratch (static device globals; no allocation) ----------------
__device__ float g_A[NEDGE * HDIM];        // ssp(ea@W1+b1), per layer (157 MB)
__device__ float g_eattr[NEDGE * EA_LD];   // gaussian smearing (13.6 MB)
__device__ float g_h[2][NNODES * HDIM];    // node features ping-pong
__device__ float g_x1[NNODES * HDIM];
__device__ float g_msg[NNODES * HDIM];
__device__ float g_t[NNODES * HDIM];
__device__ int   g_nbr[NEDGE];
__device__ float g_C[NEDGE];
__device__ float g_d[NEDGE];
__device__ float g_pooled[NBG * HDIM];

// ---------------- shifted softplus ----------------
__device__ __forceinline__ float sspf(float x) {
    float u = x * x;
    if (u < 1.0f) {
        float p = fmaf(u, -2.6356299e-5f, 3.4722222e-4f);
        p = fmaf(u, p, -5.2083333e-3f);
        p = fmaf(u, p, 0.125f);
        return fmaf(u, p, 0.5f * x);
    }
    return fmaxf(x, 0.f) + log1pf(expf(-fabsf(x))) - 0.69314718056f;
}

// ---------------- tf32 helpers ----------------
__device__ __forceinline__ unsigned f2tf32(float x) {
    unsigned r;
    asm("cvt.rna.tf32.f32 %0, %1;" : "=r"(r) : "f"(x));
    return r;
}
__device__ __forceinline__ void mma_tf32(float& c0, float& c1, float& c2, float& c3,
                                         unsigned a0, unsigned a1, unsigned a2, unsigned a3,
                                         unsigned b0, unsigned b1) {
    asm("mma.sync.aligned.m16n8k8.row.col.f32.tf32.tf32.f32 "
        "{%0,%1,%2,%3}, {%4,%5,%6,%7}, {%8,%9}, {%0,%1,%2,%3};"
        : "+f"(c0), "+f"(c1), "+f"(c2), "+f"(c3)
        : "r"(a0), "r"(a1), "r"(a2), "r"(a3), "r"(b0), "r"(b1));
}

// ---------------- graph build: one warp per node ----------------
__global__ void build_graph_kernel(const float* __restrict__ pos,
                                   int* __restrict__ nbr,
                                   float* __restrict__ dbuf,
                                   float* __restrict__ cbuf) {
    __shared__ float spos[NPGC * 3];
    const int t = threadIdx.x;
    const int w = t >> 5, lane = t & 31;
    const int node = blockIdx.x * 8 + w;
    const int g = node >> 7;
    const int i = node & 127;

    for (int idx = t; idx < NPGC * 3; idx += blockDim.x)
        spos[idx] = pos[g * NPGC * 3 + idx];
    __syncthreads();

    const float px = spos[i*3+0], py = spos[i*3+1], pz = spos[i*3+2];
    float d2v[4];
#pragma unroll
    for (int c = 0; c < 4; c++) {
        int j = lane + 32 * c;
        float dx = px - spos[j*3+0];
        float dy = py - spos[j*3+1];
        float dz = pz - spos[j*3+2];
        float d2 = fmaf(dx, dx, fmaf(dy, dy, dz * dz));
        bool ok = (j != i) && (d2 <= 100.0f);
        d2v[c] = ok ? d2 : FLT_MAX;
    }

    const float PIF = 3.14159265358979f;
    for (int slot = 0; slot < KNBR; slot++) {
        float mv = d2v[0]; int mc = 0;
#pragma unroll
        for (int c = 1; c < 4; c++) if (d2v[c] < mv) { mv = d2v[c]; mc = c; }
        int mj = lane + 32 * mc;
#pragma unroll
        for (int off = 16; off > 0; off >>= 1) {
            float ov = __shfl_down_sync(0xFFFFFFFFu, mv, off);
            int   oj = __shfl_down_sync(0xFFFFFFFFu, mj, off);
            if (ov < mv || (ov == mv && oj < mj)) { mv = ov; mj = oj; }
        }
        mv = __shfl_sync(0xFFFFFFFFu, mv, 0);
        mj = __shfl_sync(0xFFFFFFFFu, mj, 0);
        if (lane == (mj & 31)) d2v[mj >> 5] = FLT_MAX;
        if (lane == 0) {
            int e = node * KNBR + slot;
            if (mv < 1e37f) {
                nbr[e] = g * NPGC + mj;
                float d = sqrtf(mv);
                dbuf[e] = d;
                cbuf[e] = 0.5f * (cosf(d * PIF / 10.0f) + 1.0f);
            } else {
                nbr[e] = node;
                dbuf[e] = 0.f;
                cbuf[e] = 0.f;
            }
        }
    }
}

// ---------------- gaussian smearing ----------------
__global__ void edge_feat_kernel(const float* __restrict__ dbuf,
                                 float* __restrict__ eattr) {
    int idx = blockIdx.x * blockDim.x + threadIdx.x;
    if (idx >= NEDGE * EA_LD) return;
    int e = idx / EA_LD;
    int c = idx - e * EA_LD;
    float v = 0.f;
    if (c < GDIM) {
        const float step = 10.0f / 49.0f;
        const float coeff = -0.5f / (step * step);
        float t = dbuf[e] - c * step;
        v = __expf(coeff * t * t);
    }
    eattr[idx] = v;
}

// ---------------- embedding gather ----------------
__global__ void embed_kernel(const float* __restrict__ emb,
                             const int* __restrict__ z,
                             float* __restrict__ h) {
    int idx = blockIdx.x * blockDim.x + threadIdx.x;
    if (idx >= NNODES * HDIM) return;
    int n = idx / HDIM, c = idx - n * HDIM;
    h[idx] = emb[z[n] * HDIM + c];
}

// ---------------- generic GEMM (R11 known-good FFMA version) ----------------
#define BM 128
#define BN 64
#define BK 16

template<int EPI>
__global__ __launch_bounds__(256) void gemm_kernel(
    const float* __restrict__ X, int ldx, int kx, int kw,
    const float* __restrict__ W,
    const float* __restrict__ bias,
    const float* __restrict__ res,
    float* __restrict__ out)
{
    __shared__ float Xs[BK][BM + 4];
    __shared__ float Ws[BK][BN + 4];
    const int t = threadIdx.x;
    const int ty = t >> 4, tx = t & 15;
    const int row0 = blockIdx.x * BM;
    const int h0 = blockIdx.y * BN;

    float acc[8][4];
#pragma unroll
    for (int i = 0; i < 8; i++)
#pragma unroll
        for (int j = 0; j < 4; j++) acc[i][j] = 0.f;

    const int kmax = (kx > kw) ? kx : kw;
    const int nStages = (kmax + BK - 1) / BK;

    const int xkoff = (t & 1) * 8;
    const float* Xrow = X + (size_t)(row0 + (t >> 1)) * ldx;
    const int wk = ty;
    const int wcol = tx * 4;
    const bool wcolOk = (h0 + wcol) < HDIM;

    float4 xr0, xr1, wr;
    const float4 f4z = make_float4(0.f, 0.f, 0.f, 0.f);

    auto loadStage = [&](int k0) {
        int kc = k0 + xkoff;
        xr0 = (kc < kx) ? *(const float4*)(Xrow + kc) : f4z;
        xr1 = (kc + 4 < kx) ? *(const float4*)(Xrow + kc + 4) : f4z;
        int kr = k0 + wk;
        wr = (kr < kw && wcolOk) ? *(const float4*)(W + (size_t)kr * HDIM + h0 + wcol) : f4z;
    };
    auto stsStage = [&]() {
        int rl = t >> 1;
#pragma unroll
        for (int j = 0; j < 4; j++) Xs[xkoff + j][rl] = (&xr0.x)[j];
#pragma unroll
        for (int j = 0; j < 4; j++) Xs[xkoff + 4 + j][rl] = (&xr1.x)[j];
        *(float4*)&Ws[wk][wcol] = wr;
    };

    loadStage(0);
    stsStage();
    __syncthreads();

    for (int s = 0; s < nStages; ++s) {
        if (s + 1 < nStages) loadStage((s + 1) * BK);
#pragma unroll
        for (int kk = 0; kk < BK; ++kk) {
            float4 b = *(const float4*)&Ws[kk][tx * 4];
            float4 a0 = *(const float4*)&Xs[kk][ty * 8];
            float4 a1 = *(const float4*)&Xs[kk][ty * 8 + 4];
            float av[8] = {a0.x, a0.y, a0.z, a0.w, a1.x, a1.y, a1.z, a1.w};
#pragma unroll
            for (int i = 0; i < 8; i++) {
                acc[i][0] = fmaf(av[i], b.x, acc[i][0]);
                acc[i][1] = fmaf(av[i], b.y, acc[i][1]);
                acc[i][2] = fmaf(av[i], b.z, acc[i][2]);
                acc[i][3] = fmaf(av[i], b.w, acc[i][3]);
            }
        }
        __syncthreads();
        if (s + 1 < nStages) { stsStage(); __syncthreads(); }
    }

    if (!wcolOk) return;
    float4 bb = f4z;
    if (EPI >= 1) bb = *(const float4*)&bias[h0 + wcol];
#pragma unroll
    for (int i = 0; i < 8; i++) {
        size_t r = (size_t)(row0 + ty * 8 + i);
        float4 v;
        v.x = acc[i][0] + bb.x; v.y = acc[i][1] + bb.y;
        v.z = acc[i][2] + bb.z; v.w = acc[i][3] + bb.w;
        if (EPI == 1) { v.x = sspf(v.x); v.y = sspf(v.y); v.z = sspf(v.z); v.w = sspf(v.w); }
        if (EPI == 2) {
            float4 rv = *(const float4*)&res[r * HDIM + h0 + wcol];
            v.x += rv.x; v.y += rv.y; v.z += rv.z; v.w += rv.w;
        }
        *(float4*)&out[r * HDIM + h0 + wcol] = v;
    }
}

// ---------------- fused edge GEMM + aggregate, tf32 mma.sync ----------------
// block = 128 edges (2 nodes) x 64 h-cols, 256 threads = 8 warps (4 along M x 2 along N).
// Wf = A@W2 + b2 ; msg[n,h] = sum_k C[e] * x1[nbr[e],h] * Wf[e,h]
#define AS_LD 20    // As row stride (floats): conflict-free fragment loads
#define WS_LD 72    // Ws row stride
#define WF_LD 68    // Wf staging row stride

__global__ __launch_bounds__(256) void edge_agg_kernel(
    const float* __restrict__ A, const float* __restrict__ W2,
    const float* __restrict__ b2, const float* __restrict__ x1,
    const int* __restrict__ nbr, const float* __restrict__ C,
    float* __restrict__ msg)
{
    // union: mainloop tiles (As 128x20 + Ws 16x72 = 14848 B) overlaid with
    // Wf staging (128x68 = 34816 B); live ranges separated by __syncthreads.
    __shared__ __align__(16) char smembuf[BM * WF_LD * 4];   // 34816 B
    __shared__ float red[16][BN + 4];
    unsigned (*As)[AS_LD] = (unsigned (*)[AS_LD])smembuf;                 // [128][20]
    unsigned (*Ws)[WS_LD] = (unsigned (*)[WS_LD])(smembuf + BM*AS_LD*4);  // [16][72]
    float    (*Wfs)[WF_LD] = (float (*)[WF_LD])smembuf;                   // [128][68]

    const int t = threadIdx.x;
    const int lane = t & 31, wid = t >> 5;
    const int wm = wid & 3, wn = wid >> 2;     // warp pos: M(4) x N(2)
    const int l4 = lane >> 2, lg = lane & 3;
    const int erow0 = blockIdx.x * BM;
    const int h0 = blockIdx.y * BN;

    float acc[2][4][4];
#pragma unroll
    for (int mt = 0; mt < 2; mt++)
#pragma unroll
        for (int nt = 0; nt < 4; nt++)
#pragma unroll
            for (int j = 0; j < 4; j++) acc[mt][nt][j] = 0.f;

    const int nStages = (HDIM + BK - 1) / BK;   // 38
    const int xrl = t >> 1;
    const int xkoff = (t & 1) * 8;
    const float* Xrow = A + (size_t)(erow0 + xrl) * HDIM;
    const int wk = t >> 4;                      // 0..15 (k row of Ws)
    const int wcol = (t & 15) * 4;
    const bool wcolOk = (h0 + wcol) < HDIM;

    float4 xr0, xr1, wr;
    const float4 f4z = make_float4(0.f, 0.f, 0.f, 0.f);

    auto loadStage = [&](int k0) {
        int kc = k0 + xkoff;
        xr0 = (kc < HDIM) ? *(const float4*)(Xrow + kc) : f4z;
        xr1 = (kc + 4 < HDIM) ? *(const float4*)(Xrow + kc + 4) : f4z;
        int kr = k0 + wk;
        wr = (kr < HDIM && wcolOk) ? *(const float4*)(W2 + (size_t)kr * HDIM + h0 + wcol) : f4z;
    };
    auto stsStage = [&]() {
#pragma unroll
        for (int j = 0; j < 4; j++) As[xrl][xkoff + j]     = f2tf32((&xr0.x)[j]);
#pragma unroll
        for (int j = 0; j < 4; j++) As[xrl][xkoff + 4 + j] = f2tf32((&xr1.x)[j]);
#pragma unroll
        for (int j = 0; j < 4; j++) Ws[wk][wcol + j] = f2tf32((&wr.x)[j]);
    };

    loadStage(0);
    stsStage();
    __syncthreads();

    for (int s = 0; s < nStages; ++s) {
        if (s + 1 < nStages) loadStage((s + 1) * BK);
#pragma unroll
        for (int ks2 = 0; ks2 < 2; ++ks2) {
            const int ks = ks2 * 8;
            unsigned af[2][4];
#pragma unroll
            for (int mt = 0; mt < 2; mt++) {
                int rb = wm * 32 + mt * 16;
                af[mt][0] = As[rb + l4][ks + lg];
                af[mt][1] = As[rb + 8 + l4][ks + lg];
                af[mt][2] = As[rb + l4][ks + lg + 4];
                af[mt][3] = As[rb + 8 + l4][ks + lg + 4];
            }
            unsigned bf[4][2];
#pragma unroll
            for (int nt = 0; nt < 4; nt++) {
                int col = wn * 32 + nt * 8 + l4;
                bf[nt][0] = Ws[ks + lg][col];
                bf[nt][1] = Ws[ks + 4 + lg][col];
            }
#pragma unroll
            for (int mt = 0; mt < 2; mt++)
#pragma unroll
                for (int nt = 0; nt < 4; nt++)
                    mma_tf32(acc[mt][nt][0], acc[mt][nt][1], acc[mt][nt][2], acc[mt][nt][3],
                             af[mt][0], af[mt][1], af[mt][2], af[mt][3],
                             bf[nt][0], bf[nt][1]);
        }
        __syncthreads();
        if (s + 1 < nStages) { stsStage(); __syncthreads(); }
    }

    // stage D fragments to smem (overlays As/Ws — sync above ensures all reads done)
#pragma unroll
    for (int mt = 0; mt < 2; mt++) {
        int r0 = wm * 32 + mt * 16 + l4;
#pragma unroll
        for (int nt = 0; nt < 4; nt++) {
            int c0 = wn * 32 + nt * 8 + 2 * lg;
            *(float2*)&Wfs[r0][c0]     = make_float2(acc[mt][nt][0], acc[mt][nt][1]);
            *(float2*)&Wfs[r0 + 8][c0] = make_float2(acc[mt][nt][2], acc[mt][nt][3]);
        }
    }
    __syncthreads();

    // epilogue (verified R11 structure): +b2, *C, *x1[nbr], reduce edges->node
    const int ty = t >> 4, tx = t & 15;
    float part[4] = {0.f, 0.f, 0.f, 0.f};
    float4 bb = wcolOk ? *(const float4*)&b2[h0 + wcol] : f4z;
    if (wcolOk) {
#pragma unroll
        for (int i = 0; i < 8; i++) {
            int e = erow0 + ty * 8 + i;
            float ce = C[e];
            if (ce != 0.f) {
                int nb = nbr[e];
                float4 wf = *(const float4*)&Wfs[ty * 8 + i][tx * 4];
                float4 xv = *(const float4*)&x1[(size_t)nb * HDIM + h0 + wcol];
                part[0] = fmaf((wf.x + bb.x) * ce, xv.x, part[0]);
                part[1] = fmaf((wf.y + bb.y) * ce, xv.y, part[1]);
                part[2] = fmaf((wf.z + bb.z) * ce, xv.z, part[2]);
                part[3] = fmaf((wf.w + bb.w) * ce, xv.w, part[3]);
            }
        }
    }
    __syncthreads();
    *(float4*)&red[ty][tx * 4] = make_float4(part[0], part[1], part[2], part[3]);
    __syncthreads();
    if (t < 128) {
        int half = t >> 6;
        int col = t & 63;
        if (h0 + col < HDIM) {
            float s = 0.f;
#pragma unroll
            for (int i = 0; i < 8; i++) s += red[half * 8 + i][col];
            msg[(size_t)(blockIdx.x * 2 + half) * HDIM + h0 + col] = s;
        }
    }
}

// ---------------- mean pool per graph ----------------
__global__ void pool_kernel(const float* __restrict__ h, float* __restrict__ pooled) {
    int b = blockIdx.x;
    int c = threadIdx.x;
    if (c >= HDIM) return;
    float s = 0.f;
    for (int n = 0; n < NPGC; n++) s += h[(size_t)(b * NPGC + n) * HDIM + c];
    pooled[b * HDIM + c] = s * (1.0f / 128.0f);
}

// ---------------- final linear ----------------
__global__ void out_kernel(const float* __restrict__ pooled,
                           const float* __restrict__ pw,
                           const float* __restrict__ pb,
                           float* __restrict__ out) {
    __shared__ float prow[HDIM];
    int b = blockIdx.x;
    for (int i = threadIdx.x; i < HDIM; i += blockDim.x)
        prow[i] = pooled[b * HDIM + i];
    __syncthreads();
    int c = blockIdx.y * 128 + threadIdx.x;
    if (c < HDIM) {
        float s = pb[c];
        for (int k = 0; k < HDIM; k++)
            s = fmaf(prow[k], pw[k * HDIM + c], s);
        out[b * HDIM + c] = s;
    }
}

// ---------------- host launcher ----------------
extern "C" void kernel_launch(void* const* d_in, const int* in_sizes, int n_in,
                              void* d_out, int out_size) {
    int zi, pi, base;
    if (in_sizes[0] == NNODES) { zi = 0; pi = 1; base = 2; }
    else                       { pi = 0; base = 1; zi = n_in - 1; }

    const int*   z   = (const int*)d_in[zi];
    const float* pos = (const float*)d_in[pi];
    const float* emb = (const float*)d_in[base + 0];
    const float* w1  = (const float*)d_in[base + 1];
    const float* b1  = (const float*)d_in[base + 2];
    const float* w2  = (const float*)d_in[base + 3];
    const float* b2  = (const float*)d_in[base + 4];
    const float* l1w = (const float*)d_in[base + 5];
    const float* l2w = (const float*)d_in[base + 6];
    const float* l2b = (const float*)d_in[base + 7];
    const float* ilw = (const float*)d_in[base + 8];
    const float* ilb = (const float*)d_in[base + 9];
    const float* pw  = (const float*)d_in[base + 10];
    const float* pb  = (const float*)d_in[base + 11];
    float* out = (float*)d_out;

    void* p;
    float *A, *ea, *hbase, *x1, *msgb, *tb, *pooled, *Cb, *db; int* nbrp;
    cudaGetSymbolAddress(&p, g_A);      A = (float*)p;
    cudaGetSymbolAddress(&p, g_eattr);  ea = (float*)p;
    cudaGetSymbolAddress(&p, g_h);      hbase = (float*)p;
    cudaGetSymbolAddress(&p, g_x1);     x1 = (float*)p;
    cudaGetSymbolAddress(&p, g_msg);    msgb = (float*)p;
    cudaGetSymbolAddress(&p, g_t);      tb = (float*)p;
    cudaGetSymbolAddress(&p, g_nbr);    nbrp = (int*)p;
    cudaGetSymbolAddress(&p, g_C);      Cb = (float*)p;
    cudaGetSymbolAddress(&p, g_d);      db = (float*)p;
    cudaGetSymbolAddress(&p, g_pooled); pooled = (float*)p;

    float* h0 = hbase;
    float* h1 = hbase + (size_t)NNODES * HDIM;

    build_graph_kernel<<<128, 256>>>(pos, nbrp, db, Cb);
    edge_feat_kernel<<<(NEDGE * EA_LD + 255) / 256, 256>>>(db, ea);
    embed_kernel<<<(NNODES * HDIM + 255) / 256, 256>>>(emb, z, h0);

    float* hc = h0;
    float* hn = h1;
    for (int l = 0; l < LAY; l++) {
        // x1 = h @ lin1_w (no bias)
        gemm_kernel<0><<<dim3(NNODES / BM, 10), 256>>>(
            hc, HDIM, HDIM, HDIM, l1w + (size_t)l * HDIM * HDIM, nullptr, nullptr, x1);
        // A = ssp(ea @ W1 + b1)
        gemm_kernel<1><<<dim3(NEDGE / BM, 10), 256>>>(
            ea, EA_LD, EA_LD, GDIM, w1 + (size_t)l * GDIM * HDIM, b1 + l * HDIM, nullptr, A);
        // msg = sum_k C * x1[nbr] * (A @ W2 + b2)   [tf32 tensor-core path]
        edge_agg_kernel<<<dim3(NNODES / 2, 10), 256>>>(
            A, w2 + (size_t)l * HDIM * HDIM, b2 + l * HDIM, x1, nbrp, Cb, msgb);
        // t = ssp(msg @ lin2_w + lin2_b)
        gemm_kernel<1><<<dim3(NNODES / BM, 10), 256>>>(
            msgb, HDIM, HDIM, HDIM, l2w + (size_t)l * HDIM * HDIM, l2b + l * HDIM, nullptr, tb);
        // h_new = h + t @ int_lin_w + int_lin_b
        gemm_kernel<2><<<dim3(NNODES / BM, 10), 256>>>(
            tb, HDIM, HDIM, HDIM, ilw + (size_t)l * HDIM * HDIM, ilb + l * HDIM, hc, hn);
        float* tmp = hc; hc = hn; hn = tmp;
    }

    pool_kernel<<<NBG, 640>>>(hc, pooled);
    out_kernel<<<dim3(NBG, 5), 128>>>(pooled, pw, pb, out);
}